// round 1
// baseline (speedup 1.0000x reference)
#include <cuda_runtime.h>

#define W0 4096
#define OUTW 1024
#define MAXMIP 8

// Mip chain storage for levels 1..8 (3 channels, fp32).
// Sizes: 2048^2,1024^2,512^2,256^2,128^2,64^2,32^2,16^2 texels * 3 = 16,776,960 floats (~67MB)
__device__ float g_mips[16776960];

// Byte-offset (in floats) of each mip level within g_mips. Index 0 unused (level 0 = input).
__device__ const int MIP_OFF[9] = {
    0,          // level 0: the raw input (not in g_mips)
    0,          // level 1: 2048^2*3 = 12,582,912
    12582912,   // level 2: 1024^2*3 =  3,145,728
    15728640,   // level 3:  512^2*3 =    786,432
    16515072,   // level 4:  256^2*3 =    196,608
    16711680,   // level 5:  128^2*3 =     49,152
    16760832,   // level 6:   64^2*3 =     12,288
    16773120,   // level 7:   32^2*3 =      3,072
    16776192    // level 8:   16^2*3 =        768
};

// 2x2 box-filter downsample: produce level `lvl` (>=1) from level lvl-1.
__global__ void vt_downsample(const float* __restrict__ data, int lvl) {
    const int dw = W0 >> lvl;            // destination width == height
    const int total = dw * dw;
    int i = blockIdx.x * blockDim.x + threadIdx.x;
    if (i >= total) return;

    const float* __restrict__ src = (lvl == 1) ? data : (g_mips + MIP_OFF[lvl - 1]);
    float* __restrict__ dst = g_mips + MIP_OFF[lvl];

    int x = i % dw;
    int y = i / dw;
    int sw = dw * 2;

    const float* r0 = src + ((size_t)(2 * y) * sw + 2 * x) * 3;
    const float* r1 = r0 + (size_t)sw * 3;

#pragma unroll
    for (int c = 0; c < 3; c++) {
        dst[(size_t)i * 3 + c] =
            (r0[c] + r0[3 + c] + r1[c] + r1[3 + c]) * 0.25f;
    }
}

// Bilinear fetch with wrap addressing on a square w x w, 3-channel texture.
__device__ __forceinline__ void vt_bilinear(const float* __restrict__ tex, int w,
                                            float u, float v, float rgb[3]) {
    float x = u * (float)w - 0.5f;
    float y = v * (float)w - 0.5f;
    float x0f = floorf(x);
    float y0f = floorf(y);
    float fx = x - x0f;
    float fy = y - y0f;
    int x0 = (int)x0f;
    int y0 = (int)y0f;
    // u,v in [0,1) => x0 in [-1, w-1]; a single wrap add suffices
    if (x0 < 0) x0 += w;
    if (y0 < 0) y0 += w;
    int x1 = x0 + 1; if (x1 == w) x1 = 0;
    int y1 = y0 + 1; if (y1 == w) y1 = 0;

    const float* p00 = tex + ((size_t)y0 * w + x0) * 3;
    const float* p01 = tex + ((size_t)y0 * w + x1) * 3;
    const float* p10 = tex + ((size_t)y1 * w + x0) * 3;
    const float* p11 = tex + ((size_t)y1 * w + x1) * 3;

    float w00 = (1.0f - fx) * (1.0f - fy);
    float w01 = fx * (1.0f - fy);
    float w10 = (1.0f - fx) * fy;
    float w11 = fx * fy;

#pragma unroll
    for (int c = 0; c < 3; c++) {
        rgb[c] = p00[c] * w00 + p01[c] * w01 + p10[c] * w10 + p11[c] * w11;
    }
}

__global__ void vt_sample(const float* __restrict__ data,
                          const float* __restrict__ texc,
                          const float* __restrict__ deriv,
                          float* __restrict__ out) {
    int i = blockIdx.x * blockDim.x + threadIdx.x;
    if (i >= OUTW * OUTW) return;

    float u = texc[2 * i + 0];
    float v = texc[2 * i + 1];

    float dudx = deriv[4 * i + 0] * (float)W0;
    float dvdx = deriv[4 * i + 1] * (float)W0;
    float dudy = deriv[4 * i + 2] * (float)W0;
    float dvdy = deriv[4 * i + 3] * (float)W0;

    float rho2 = fmaxf(dudx * dudx + dvdx * dvdx, dudy * dudy + dvdy * dvdy);
    float lod = 0.5f * log2f(fmaxf(rho2, 1e-20f));
    lod = fminf(fmaxf(lod, 0.0f), (float)MAXMIP);

    int l0 = (int)floorf(lod);
    if (l0 > MAXMIP) l0 = MAXMIP;          // paranoia for lod == 8.0
    float frac = lod - (float)l0;
    int l1 = (l0 < MAXMIP) ? (l0 + 1) : MAXMIP;

    const float* t0 = (l0 == 0) ? data : (g_mips + MIP_OFF[l0]);
    const float* t1 = (l1 == 0) ? data : (g_mips + MIP_OFF[l1]);

    float a[3], b[3];
    vt_bilinear(t0, W0 >> l0, u, v, a);
    vt_bilinear(t1, W0 >> l1, u, v, b);

    float w0 = 1.0f - frac;
#pragma unroll
    for (int c = 0; c < 3; c++) {
        out[(size_t)3 * i + c] = a[c] * w0 + b[c] * frac;
    }
}

extern "C" void kernel_launch(void* const* d_in, const int* in_sizes, int n_in,
                              void* d_out, int out_size) {
    const float* data  = (const float*)d_in[0];   // [1,4096,4096,3]
    const float* texc  = (const float*)d_in[1];   // [1,1024,1024,2]
    const float* deriv = (const float*)d_in[2];   // [1,1024,1024,4]
    float* out = (float*)d_out;                   // [1,1024,1024,3]

    (void)in_sizes; (void)n_in; (void)out_size;

    // Build mip chain: level l from level l-1
    for (int lvl = 1; lvl <= MAXMIP; lvl++) {
        int dw = W0 >> lvl;
        int total = dw * dw;
        int block = 256;
        int grid = (total + block - 1) / block;
        vt_downsample<<<grid, block>>>(data, lvl);
    }

    // Trilinear sample
    {
        int total = OUTW * OUTW;
        int block = 256;
        int grid = (total + block - 1) / block;
        vt_sample<<<grid, block>>>(data, texc, deriv, out);
    }
}

// round 2
// speedup vs baseline: 1.1405x; 1.1405x over previous
#include <cuda_runtime.h>

#define W0 4096
#define OUTW 1024
#define MAXMIP 8

// Mip chain storage for levels 1..8 (3 channels, fp32). ~67MB.
__device__ float g_mips[16776960];

// Offsets (in floats) of each mip level within g_mips. Level 0 = input.
__device__ const int MIP_OFF[9] = {
    0,          // level 0: raw input (not in g_mips)
    0,          // level 1: 2048^2*3
    12582912,   // level 2: 1024^2*3
    15728640,   // level 3:  512^2*3
    16515072,   // level 4:  256^2*3
    16711680,   // level 5:  128^2*3
    16760832,   // level 6:   64^2*3
    16773120,   // level 7:   32^2*3
    16776192    // level 8:   16^2*3
};

__device__ __forceinline__ void load12(float* r, const float4* p) {
    float4 f0 = p[0], f1 = p[1], f2 = p[2];
    r[0] = f0.x; r[1]  = f0.y; r[2]  = f0.z; r[3]  = f0.w;
    r[4] = f1.x; r[5]  = f1.y; r[6]  = f1.z; r[7]  = f1.w;
    r[8] = f2.x; r[9]  = f2.y; r[10] = f2.z; r[11] = f2.w;
}

// Fused 2-level downsample: from level `lvl` produce levels lvl+1 and lvl+2.
// One thread = one (lvl+2) texel = 2x2 (lvl+1) texels = 4x4 source texels.
__global__ void vt_down2(const float* __restrict__ data, int lvl) {
    const int w2 = W0 >> (lvl + 2);      // coarser output width
    const int total = w2 * w2;
    int i = blockIdx.x * blockDim.x + threadIdx.x;
    if (i >= total) return;

    const float* __restrict__ src = (lvl == 0) ? data : (g_mips + MIP_OFF[lvl]);
    float* __restrict__ d1 = g_mips + MIP_OFF[lvl + 1];
    float* __restrict__ d2 = g_mips + MIP_OFF[lvl + 2];

    int x2 = i % w2;
    int y2 = i / w2;
    const int w1 = w2 * 2;
    const int pitch4 = 3 * w2;                 // source row pitch in float4 (= sw*3/4)
    const float4* s4 = reinterpret_cast<const float4*>(src)
                       + (size_t)4 * y2 * pitch4 + 3 * x2;

    float a[12], b[12];
    float l1a[6], l1b[6];

    // rows 0,1 -> l1 row 0
    load12(a, s4);
    load12(b, s4 + pitch4);
#pragma unroll
    for (int dx = 0; dx < 2; dx++)
#pragma unroll
        for (int c = 0; c < 3; c++)
            l1a[3 * dx + c] = (a[6 * dx + c] + a[6 * dx + 3 + c] +
                               b[6 * dx + c] + b[6 * dx + 3 + c]) * 0.25f;

    // rows 2,3 -> l1 row 1
    load12(a, s4 + 2 * pitch4);
    load12(b, s4 + 3 * pitch4);
#pragma unroll
    for (int dx = 0; dx < 2; dx++)
#pragma unroll
        for (int c = 0; c < 3; c++)
            l1b[3 * dx + c] = (a[6 * dx + c] + a[6 * dx + 3 + c] +
                               b[6 * dx + c] + b[6 * dx + 3 + c]) * 0.25f;

    // write level lvl+1: 2x2 texels (6 floats per row, 8B-aligned -> float2)
    {
        float* p0 = d1 + ((size_t)(2 * y2) * w1 + 2 * x2) * 3;
        float* p1 = p0 + (size_t)w1 * 3;
        float2* q0 = reinterpret_cast<float2*>(p0);
        float2* q1 = reinterpret_cast<float2*>(p1);
        q0[0] = make_float2(l1a[0], l1a[1]);
        q0[1] = make_float2(l1a[2], l1a[3]);
        q0[2] = make_float2(l1a[4], l1a[5]);
        q1[0] = make_float2(l1b[0], l1b[1]);
        q1[1] = make_float2(l1b[2], l1b[3]);
        q1[2] = make_float2(l1b[4], l1b[5]);
    }

    // write level lvl+2: 1 texel
#pragma unroll
    for (int c = 0; c < 3; c++)
        d2[(size_t)i * 3 + c] = (l1a[c] + l1a[3 + c] + l1b[c] + l1b[3 + c]) * 0.25f;
}

// Bilinear fetch with wrap addressing on a square w x w, 3-channel texture.
__device__ __forceinline__ void vt_bilinear(const float* __restrict__ tex, int w,
                                            float u, float v, float rgb[3]) {
    float x = u * (float)w - 0.5f;
    float y = v * (float)w - 0.5f;
    float x0f = floorf(x);
    float y0f = floorf(y);
    float fx = x - x0f;
    float fy = y - y0f;
    int x0 = (int)x0f;
    int y0 = (int)y0f;
    if (x0 < 0) x0 += w;
    if (y0 < 0) y0 += w;
    int x1 = x0 + 1; if (x1 == w) x1 = 0;
    int y1 = y0 + 1; if (y1 == w) y1 = 0;

    const float* p00 = tex + ((size_t)y0 * w + x0) * 3;
    const float* p01 = tex + ((size_t)y0 * w + x1) * 3;
    const float* p10 = tex + ((size_t)y1 * w + x0) * 3;
    const float* p11 = tex + ((size_t)y1 * w + x1) * 3;

    float w00 = (1.0f - fx) * (1.0f - fy);
    float w01 = fx * (1.0f - fy);
    float w10 = (1.0f - fx) * fy;
    float w11 = fx * fy;

#pragma unroll
    for (int c = 0; c < 3; c++)
        rgb[c] = p00[c] * w00 + p01[c] * w01 + p10[c] * w10 + p11[c] * w11;
}

__global__ void vt_sample(const float* __restrict__ data,
                          const float2* __restrict__ texc,
                          const float4* __restrict__ deriv,
                          float* __restrict__ out) {
    int i = blockIdx.x * blockDim.x + threadIdx.x;
    if (i >= OUTW * OUTW) return;

    float2 uv = texc[i];
    float4 d = deriv[i];

    float dudx = d.x * (float)W0;
    float dvdx = d.y * (float)W0;
    float dudy = d.z * (float)W0;
    float dvdy = d.w * (float)W0;

    float rho2 = fmaxf(dudx * dudx + dvdx * dvdx, dudy * dudy + dvdy * dvdy);
    float lod = 0.5f * __log2f(fmaxf(rho2, 1e-20f));
    lod = fminf(fmaxf(lod, 0.0f), (float)MAXMIP);

    int l0 = (int)lod;
    if (l0 > MAXMIP) l0 = MAXMIP;
    float frac = lod - (float)l0;
    int l1 = (l0 < MAXMIP) ? (l0 + 1) : MAXMIP;

    const float* t0 = (l0 == 0) ? data : (g_mips + MIP_OFF[l0]);
    const float* t1 = g_mips + MIP_OFF[l1];   // l1 >= 1 always

    float a[3], b[3];
    vt_bilinear(t0, W0 >> l0, uv.x, uv.y, a);
    vt_bilinear(t1, W0 >> l1, uv.x, uv.y, b);

    float w0 = 1.0f - frac;
#pragma unroll
    for (int c = 0; c < 3; c++)
        out[(size_t)3 * i + c] = a[c] * w0 + b[c] * frac;
}

extern "C" void kernel_launch(void* const* d_in, const int* in_sizes, int n_in,
                              void* d_out, int out_size) {
    const float* data  = (const float*)d_in[0];   // [1,4096,4096,3]
    const float2* texc = (const float2*)d_in[1];  // [1,1024,1024,2]
    const float4* deriv = (const float4*)d_in[2]; // [1,1024,1024,4]
    float* out = (float*)d_out;                   // [1,1024,1024,3]

    (void)in_sizes; (void)n_in; (void)out_size;

    // Build mip chain two levels at a time: (1,2), (3,4), (5,6), (7,8)
    for (int lvl = 0; lvl <= 6; lvl += 2) {
        int w2 = W0 >> (lvl + 2);
        int total = w2 * w2;
        int block = 256;
        int grid = (total + block - 1) / block;
        vt_down2<<<grid, block>>>(data, lvl);
    }

    // Trilinear sample
    {
        int total = OUTW * OUTW;
        int block = 256;
        int grid = (total + block - 1) / block;
        vt_sample<<<grid, block>>>(data, texc, deriv, out);
    }
}

// round 3
// speedup vs baseline: 1.3684x; 1.1998x over previous
#include <cuda_runtime.h>

#define W0 4096
#define OUTW 1024
#define MAXMIP 8

// Mip chain for levels 1..8, float4-padded texels (rgb + 0 pad). ~89.5 MB.
// Texel counts: 2048^2,1024^2,512^2,256^2,128^2,64^2,32^2,16^2 = 5,592,320
__device__ float4 g_mips4[5592320];

// Texel offset of each level within g_mips4 (level 0 = packed input, not here).
__constant__ int MIP4_OFF[9] = {
    0,          // level 0 (unused)
    0,          // level 1: 2048^2
    4194304,    // level 2: 1024^2
    5242880,    // level 3:  512^2
    5505024,    // level 4:  256^2
    5570560,    // level 5:  128^2
    5586944,    // level 6:   64^2
    5591040,    // level 7:   32^2
    5592064     // level 8:   16^2
};

__device__ __forceinline__ float4 f4avg(float4 a, float4 b, float4 c, float4 d) {
    return make_float4((a.x + b.x + c.x + d.x) * 0.25f,
                       (a.y + b.y + c.y + d.y) * 0.25f,
                       (a.z + b.z + c.z + d.z) * 0.25f,
                       0.0f);
}

__device__ __forceinline__ void load12(float* r, const float4* p) {
    float4 f0 = p[0], f1 = p[1], f2 = p[2];
    r[0] = f0.x; r[1]  = f0.y; r[2]  = f0.z; r[3]  = f0.w;
    r[4] = f1.x; r[5]  = f1.y; r[6]  = f1.z; r[7]  = f1.w;
    r[8] = f2.x; r[9]  = f2.y; r[10] = f2.z; r[11] = f2.w;
}

// Kernel A: base (packed rgb) -> levels 1 and 2 (float4 texels).
// One thread = one L2 texel = 2x2 L1 texels = 4x4 base texels.
__global__ void vt_downA(const float* __restrict__ data) {
    const int w2 = W0 >> 2;              // 1024
    int i = blockIdx.x * blockDim.x + threadIdx.x;
    if (i >= w2 * w2) return;

    float4* __restrict__ d1 = g_mips4;               // level 1
    float4* __restrict__ d2 = g_mips4 + 4194304;     // level 2

    int x2 = i & (w2 - 1);
    int y2 = i >> 10;
    const int w1 = w2 * 2;
    const int pitch4 = 3 * w2;           // base row pitch in float4 (4096*3/4)
    const float4* s4 = reinterpret_cast<const float4*>(data)
                       + (size_t)4 * y2 * pitch4 + 3 * x2;

    float a[12], b[12];
    float4 l1[4];

#pragma unroll
    for (int half = 0; half < 2; half++) {
        load12(a, s4 + (2 * half) * pitch4);
        load12(b, s4 + (2 * half + 1) * pitch4);
#pragma unroll
        for (int dx = 0; dx < 2; dx++) {
            l1[2 * half + dx] = make_float4(
                (a[6 * dx + 0] + a[6 * dx + 3] + b[6 * dx + 0] + b[6 * dx + 3]) * 0.25f,
                (a[6 * dx + 1] + a[6 * dx + 4] + b[6 * dx + 1] + b[6 * dx + 4]) * 0.25f,
                (a[6 * dx + 2] + a[6 * dx + 5] + b[6 * dx + 2] + b[6 * dx + 5]) * 0.25f,
                0.0f);
        }
    }

    // write level 1 (2x2)
    float4* p0 = d1 + (size_t)(2 * y2) * w1 + 2 * x2;
    p0[0] = l1[0]; p0[1] = l1[1];
    p0[w1] = l1[2]; p0[w1 + 1] = l1[3];

    // write level 2 (1)
    d2[i] = f4avg(l1[0], l1[1], l1[2], l1[3]);
}

// Kernel B: level 2 -> levels 3..8, one kernel. Block = 64x64 L2 tile (one L8 texel).
// Grid: 16x16 blocks of 256 threads.
__global__ void vt_downB() {
    __shared__ float4 s4[256];   // L4 tile 16x16
    __shared__ float4 s5[64];    // L5 tile 8x8
    __shared__ float4 s6[16];    // L6 tile 4x4
    __shared__ float4 s7[4];     // L7 tile 2x2

    const float4* __restrict__ L2 = g_mips4 + 4194304;
    float4* __restrict__ L3 = g_mips4 + 5242880;
    float4* __restrict__ L4 = g_mips4 + 5505024;
    float4* __restrict__ L5 = g_mips4 + 5570560;
    float4* __restrict__ L6 = g_mips4 + 5586944;
    float4* __restrict__ L7 = g_mips4 + 5591040;
    float4* __restrict__ L8 = g_mips4 + 5592064;

    int t = threadIdx.x;
    int bx = blockIdx.x, by = blockIdx.y;
    int tx = t & 15, ty = t >> 4;

    // Each thread: 4x4 L2 texels at (64bx + 4tx, 64by + 4ty)
    {
        int x0 = 64 * bx + 4 * tx;
        int y0 = 64 * by + 4 * ty;
        const float4* src = L2 + (size_t)y0 * 1024 + x0;

        float4 r[4][4];
#pragma unroll
        for (int dy = 0; dy < 4; dy++)
#pragma unroll
            for (int dx = 0; dx < 4; dx++)
                r[dy][dx] = src[(size_t)dy * 1024 + dx];

        // 2x2 L3 texels
        float4 l3[4];
#pragma unroll
        for (int dy = 0; dy < 2; dy++)
#pragma unroll
            for (int dx = 0; dx < 2; dx++)
                l3[2 * dy + dx] = f4avg(r[2 * dy][2 * dx], r[2 * dy][2 * dx + 1],
                                        r[2 * dy + 1][2 * dx], r[2 * dy + 1][2 * dx + 1]);

        int x3 = 32 * bx + 2 * tx;
        int y3 = 32 * by + 2 * ty;
        float4* p = L3 + (size_t)y3 * 512 + x3;
        p[0] = l3[0]; p[1] = l3[1];
        p[512] = l3[2]; p[513] = l3[3];

        // 1 L4 texel
        float4 l4 = f4avg(l3[0], l3[1], l3[2], l3[3]);
        L4[(size_t)(16 * by + ty) * 256 + (16 * bx + tx)] = l4;
        s4[ty * 16 + tx] = l4;
    }
    __syncthreads();

    if (t < 64) {
        int x = t & 7, y = t >> 3;
        float4 v = f4avg(s4[(2 * y) * 16 + 2 * x], s4[(2 * y) * 16 + 2 * x + 1],
                         s4[(2 * y + 1) * 16 + 2 * x], s4[(2 * y + 1) * 16 + 2 * x + 1]);
        L5[(size_t)(8 * by + y) * 128 + (8 * bx + x)] = v;
        s5[y * 8 + x] = v;
    }
    __syncthreads();

    if (t < 16) {
        int x = t & 3, y = t >> 2;
        float4 v = f4avg(s5[(2 * y) * 8 + 2 * x], s5[(2 * y) * 8 + 2 * x + 1],
                         s5[(2 * y + 1) * 8 + 2 * x], s5[(2 * y + 1) * 8 + 2 * x + 1]);
        L6[(size_t)(4 * by + y) * 64 + (4 * bx + x)] = v;
        s6[y * 4 + x] = v;
    }
    __syncthreads();

    if (t < 4) {
        int x = t & 1, y = t >> 1;
        float4 v = f4avg(s6[(2 * y) * 4 + 2 * x], s6[(2 * y) * 4 + 2 * x + 1],
                         s6[(2 * y + 1) * 4 + 2 * x], s6[(2 * y + 1) * 4 + 2 * x + 1]);
        L7[(size_t)(2 * by + y) * 32 + (2 * bx + x)] = v;
        s7[y * 2 + x] = v;
    }
    __syncthreads();

    if (t == 0) {
        float4 v = f4avg(s7[0], s7[1], s7[2], s7[3]);
        L8[(size_t)by * 16 + bx] = v;
    }
}

// Bilinear fetch (wrap) from float4-padded mip storage.
__device__ __forceinline__ void vt_bilinear4(const float4* __restrict__ tex, int w,
                                             float u, float v, float rgb[3]) {
    float x = u * (float)w - 0.5f;
    float y = v * (float)w - 0.5f;
    float x0f = floorf(x);
    float y0f = floorf(y);
    float fx = x - x0f;
    float fy = y - y0f;
    int x0 = (int)x0f;
    int y0 = (int)y0f;
    if (x0 < 0) x0 += w;
    if (y0 < 0) y0 += w;
    int x1 = x0 + 1; if (x1 == w) x1 = 0;
    int y1 = y0 + 1; if (y1 == w) y1 = 0;

    float4 p00 = tex[(size_t)y0 * w + x0];
    float4 p01 = tex[(size_t)y0 * w + x1];
    float4 p10 = tex[(size_t)y1 * w + x0];
    float4 p11 = tex[(size_t)y1 * w + x1];

    float w00 = (1.0f - fx) * (1.0f - fy);
    float w01 = fx * (1.0f - fy);
    float w10 = (1.0f - fx) * fy;
    float w11 = fx * fy;

    rgb[0] = p00.x * w00 + p01.x * w01 + p10.x * w10 + p11.x * w11;
    rgb[1] = p00.y * w00 + p01.y * w01 + p10.y * w10 + p11.y * w11;
    rgb[2] = p00.z * w00 + p01.z * w01 + p10.z * w10 + p11.z * w11;
}

// Packed (rgb) bilinear for level 0 only (rare path).
__device__ __forceinline__ void vt_bilinear0(const float* __restrict__ tex, int w,
                                             float u, float v, float rgb[3]) {
    float x = u * (float)w - 0.5f;
    float y = v * (float)w - 0.5f;
    float x0f = floorf(x);
    float y0f = floorf(y);
    float fx = x - x0f;
    float fy = y - y0f;
    int x0 = (int)x0f;
    int y0 = (int)y0f;
    if (x0 < 0) x0 += w;
    if (y0 < 0) y0 += w;
    int x1 = x0 + 1; if (x1 == w) x1 = 0;
    int y1 = y0 + 1; if (y1 == w) y1 = 0;

    const float* p00 = tex + ((size_t)y0 * w + x0) * 3;
    const float* p01 = tex + ((size_t)y0 * w + x1) * 3;
    const float* p10 = tex + ((size_t)y1 * w + x0) * 3;
    const float* p11 = tex + ((size_t)y1 * w + x1) * 3;

    float w00 = (1.0f - fx) * (1.0f - fy);
    float w01 = fx * (1.0f - fy);
    float w10 = (1.0f - fx) * fy;
    float w11 = fx * fy;

#pragma unroll
    for (int c = 0; c < 3; c++)
        rgb[c] = p00[c] * w00 + p01[c] * w01 + p10[c] * w10 + p11[c] * w11;
}

__global__ void vt_sample(const float* __restrict__ data,
                          const float2* __restrict__ texc,
                          const float4* __restrict__ deriv,
                          float* __restrict__ out) {
    int i = blockIdx.x * blockDim.x + threadIdx.x;
    if (i >= OUTW * OUTW) return;

    float2 uv = texc[i];
    float4 d = deriv[i];

    float dudx = d.x * (float)W0;
    float dvdx = d.y * (float)W0;
    float dudy = d.z * (float)W0;
    float dvdy = d.w * (float)W0;

    float rho2 = fmaxf(dudx * dudx + dvdx * dvdx, dudy * dudy + dvdy * dvdy);
    float lod = 0.5f * __log2f(fmaxf(rho2, 1e-20f));
    lod = fminf(fmaxf(lod, 0.0f), (float)MAXMIP);

    int l0 = (int)lod;
    if (l0 > MAXMIP) l0 = MAXMIP;
    float frac = lod - (float)l0;
    int l1 = (l0 < MAXMIP) ? (l0 + 1) : MAXMIP;

    float a[3], b[3];
    if (l0 == 0) {
        vt_bilinear0(data, W0, uv.x, uv.y, a);
    } else {
        vt_bilinear4(g_mips4 + MIP4_OFF[l0], W0 >> l0, uv.x, uv.y, a);
    }
    vt_bilinear4(g_mips4 + MIP4_OFF[l1], W0 >> l1, uv.x, uv.y, b);

    float w0 = 1.0f - frac;
    out[(size_t)3 * i + 0] = a[0] * w0 + b[0] * frac;
    out[(size_t)3 * i + 1] = a[1] * w0 + b[1] * frac;
    out[(size_t)3 * i + 2] = a[2] * w0 + b[2] * frac;
}

extern "C" void kernel_launch(void* const* d_in, const int* in_sizes, int n_in,
                              void* d_out, int out_size) {
    const float* data  = (const float*)d_in[0];   // [1,4096,4096,3]
    const float2* texc = (const float2*)d_in[1];  // [1,1024,1024,2]
    const float4* deriv = (const float4*)d_in[2]; // [1,1024,1024,4]
    float* out = (float*)d_out;                   // [1,1024,1024,3]

    (void)in_sizes; (void)n_in; (void)out_size;

    // A: base -> L1, L2
    {
        int total = 1024 * 1024;
        vt_downA<<<total / 256, 256>>>(data);
    }
    // B: L2 -> L3..L8
    {
        dim3 grid(16, 16);
        vt_downB<<<grid, 256>>>();
    }
    // Sample
    {
        int total = OUTW * OUTW;
        vt_sample<<<total / 256, 256>>>(data, texc, deriv, out);
    }
}

// round 4
// speedup vs baseline: 1.5549x; 1.1362x over previous
#include <cuda_runtime.h>
#include <cuda_fp16.h>

#define W0 4096
#define OUTW 1024
#define MAXMIP 8

// Packed half4 texel: rgb + pad, 8 bytes.
struct __align__(8) h4 { __half2 rg; __half2 bz; };

// Mip chain levels 1..8 in fp16 texels. 5,592,320 texels * 8B = ~44.7MB.
__device__ h4 g_mh[5592320];

// Texel offset of each level within g_mh (level 0 = packed fp32 input).
__constant__ int MIPH_OFF[9] = {
    0,          // level 0 (unused)
    0,          // level 1: 2048^2
    4194304,    // level 2: 1024^2
    5242880,    // level 3:  512^2
    5505024,    // level 4:  256^2
    5570560,    // level 5:  128^2
    5586944,    // level 6:   64^2
    5591040,    // level 7:   32^2
    5592064     // level 8:   16^2
};

__device__ __forceinline__ h4 pack_h4(float r, float g, float b) {
    h4 t;
    t.rg = __floats2half2_rn(r, g);
    t.bz = __floats2half2_rn(b, 0.0f);
    return t;
}

__device__ __forceinline__ float3 unpack_h4(h4 t) {
    float2 rg = __half22float2(t.rg);
    return make_float3(rg.x, rg.y, __low2float(t.bz));
}

__device__ __forceinline__ float3 f3avg(float3 a, float3 b, float3 c, float3 d) {
    return make_float3((a.x + b.x + c.x + d.x) * 0.25f,
                       (a.y + b.y + c.y + d.y) * 0.25f,
                       (a.z + b.z + c.z + d.z) * 0.25f);
}

__device__ __forceinline__ void load12(float* r, const float4* p) {
    float4 f0 = p[0], f1 = p[1], f2 = p[2];
    r[0] = f0.x; r[1]  = f0.y; r[2]  = f0.z; r[3]  = f0.w;
    r[4] = f1.x; r[5]  = f1.y; r[6]  = f1.z; r[7]  = f1.w;
    r[8] = f2.x; r[9]  = f2.y; r[10] = f2.z; r[11] = f2.w;
}

// Kernel A: base (packed fp32 rgb) -> levels 1 and 2 (fp16 texels).
// One thread = one L2 texel = 2x2 L1 texels = 4x4 base texels.
__global__ __launch_bounds__(256) void vt_downA(const float* __restrict__ data) {
    const int w2 = W0 >> 2;              // 1024
    int i = blockIdx.x * blockDim.x + threadIdx.x;
    if (i >= w2 * w2) return;

    h4* __restrict__ d1 = g_mh;                  // level 1
    h4* __restrict__ d2 = g_mh + 4194304;        // level 2

    int x2 = i & (w2 - 1);
    int y2 = i >> 10;
    const int w1 = w2 * 2;
    const int pitch4 = 3 * w2;           // base row pitch in float4
    const float4* s4 = reinterpret_cast<const float4*>(data)
                       + (size_t)4 * y2 * pitch4 + 3 * x2;

    float a[12], b[12];
    float3 l1[4];

#pragma unroll
    for (int half = 0; half < 2; half++) {
        load12(a, s4 + (2 * half) * pitch4);
        load12(b, s4 + (2 * half + 1) * pitch4);
#pragma unroll
        for (int dx = 0; dx < 2; dx++) {
            l1[2 * half + dx] = make_float3(
                (a[6 * dx + 0] + a[6 * dx + 3] + b[6 * dx + 0] + b[6 * dx + 3]) * 0.25f,
                (a[6 * dx + 1] + a[6 * dx + 4] + b[6 * dx + 1] + b[6 * dx + 4]) * 0.25f,
                (a[6 * dx + 2] + a[6 * dx + 5] + b[6 * dx + 2] + b[6 * dx + 5]) * 0.25f);
        }
    }

    // write level 1: two adjacent texels per row -> one 16B store each
    {
        h4 t00 = pack_h4(l1[0].x, l1[0].y, l1[0].z);
        h4 t01 = pack_h4(l1[1].x, l1[1].y, l1[1].z);
        h4 t10 = pack_h4(l1[2].x, l1[2].y, l1[2].z);
        h4 t11 = pack_h4(l1[3].x, l1[3].y, l1[3].z);
        uint2 u00 = *reinterpret_cast<uint2*>(&t00);
        uint2 u01 = *reinterpret_cast<uint2*>(&t01);
        uint2 u10 = *reinterpret_cast<uint2*>(&t10);
        uint2 u11 = *reinterpret_cast<uint2*>(&t11);
        h4* p0 = d1 + (size_t)(2 * y2) * w1 + 2 * x2;   // even texel -> 16B aligned
        *reinterpret_cast<uint4*>(p0)      = make_uint4(u00.x, u00.y, u01.x, u01.y);
        *reinterpret_cast<uint4*>(p0 + w1) = make_uint4(u10.x, u10.y, u11.x, u11.y);
    }

    // write level 2
    float3 l2 = f3avg(l1[0], l1[1], l1[2], l1[3]);
    d2[i] = pack_h4(l2.x, l2.y, l2.z);
}

// Kernel B: level 2 -> levels 3..8 in one kernel.
// Block = 64x64 L2 tile (one L8 texel). Grid: 16x16 blocks of 256 threads.
__global__ __launch_bounds__(256) void vt_downB() {
    __shared__ float4 s4[256];   // L4 tile 16x16
    __shared__ float4 s5[64];    // L5 tile 8x8
    __shared__ float4 s6[16];    // L6 tile 4x4
    __shared__ float4 s7[4];     // L7 tile 2x2

    const h4* __restrict__ L2t = g_mh + 4194304;
    h4* __restrict__ L3 = g_mh + 5242880;
    h4* __restrict__ L4 = g_mh + 5505024;
    h4* __restrict__ L5 = g_mh + 5570560;
    h4* __restrict__ L6 = g_mh + 5586944;
    h4* __restrict__ L7 = g_mh + 5591040;
    h4* __restrict__ L8 = g_mh + 5592064;

    int t = threadIdx.x;
    int bx = blockIdx.x, by = blockIdx.y;
    int tx = t & 15, ty = t >> 4;

    // Each thread: 4x4 L2 texels at (64bx + 4tx, 64by + 4ty); 2 uint4 loads/row.
    {
        int x0 = 64 * bx + 4 * tx;
        int y0 = 64 * by + 4 * ty;
        const uint4* src = reinterpret_cast<const uint4*>(L2t + (size_t)y0 * 1024 + x0);
        // row stride in uint4 units: 1024 texels * 8B / 16B = 512

        float3 r[4][4];
#pragma unroll
        for (int dy = 0; dy < 4; dy++) {
            uint4 q0 = src[(size_t)dy * 512];
            uint4 q1 = src[(size_t)dy * 512 + 1];
            const __half2* h0 = reinterpret_cast<const __half2*>(&q0);
            const __half2* h1 = reinterpret_cast<const __half2*>(&q1);
            float2 t0rg = __half22float2(h0[0]);
            float2 t1rg = __half22float2(h0[2]);
            float2 t2rg = __half22float2(h1[0]);
            float2 t3rg = __half22float2(h1[2]);
            r[dy][0] = make_float3(t0rg.x, t0rg.y, __low2float(h0[1]));
            r[dy][1] = make_float3(t1rg.x, t1rg.y, __low2float(h0[3]));
            r[dy][2] = make_float3(t2rg.x, t2rg.y, __low2float(h1[1]));
            r[dy][3] = make_float3(t3rg.x, t3rg.y, __low2float(h1[3]));
        }

        // 2x2 L3 texels
        float3 l3[4];
#pragma unroll
        for (int dy = 0; dy < 2; dy++)
#pragma unroll
            for (int dx = 0; dx < 2; dx++)
                l3[2 * dy + dx] = f3avg(r[2 * dy][2 * dx], r[2 * dy][2 * dx + 1],
                                        r[2 * dy + 1][2 * dx], r[2 * dy + 1][2 * dx + 1]);

        int x3 = 32 * bx + 2 * tx;
        int y3 = 32 * by + 2 * ty;
        h4* p = L3 + (size_t)y3 * 512 + x3;
        p[0]   = pack_h4(l3[0].x, l3[0].y, l3[0].z);
        p[1]   = pack_h4(l3[1].x, l3[1].y, l3[1].z);
        p[512] = pack_h4(l3[2].x, l3[2].y, l3[2].z);
        p[513] = pack_h4(l3[3].x, l3[3].y, l3[3].z);

        // 1 L4 texel
        float3 l4 = f3avg(l3[0], l3[1], l3[2], l3[3]);
        L4[(size_t)(16 * by + ty) * 256 + (16 * bx + tx)] = pack_h4(l4.x, l4.y, l4.z);
        s4[ty * 16 + tx] = make_float4(l4.x, l4.y, l4.z, 0.0f);
    }
    __syncthreads();

    if (t < 64) {
        int x = t & 7, y = t >> 3;
        float4 a = s4[(2 * y) * 16 + 2 * x],     b = s4[(2 * y) * 16 + 2 * x + 1];
        float4 c = s4[(2 * y + 1) * 16 + 2 * x], d = s4[(2 * y + 1) * 16 + 2 * x + 1];
        float4 v = make_float4((a.x + b.x + c.x + d.x) * 0.25f,
                               (a.y + b.y + c.y + d.y) * 0.25f,
                               (a.z + b.z + c.z + d.z) * 0.25f, 0.0f);
        L5[(size_t)(8 * by + y) * 128 + (8 * bx + x)] = pack_h4(v.x, v.y, v.z);
        s5[y * 8 + x] = v;
    }
    __syncthreads();

    if (t < 16) {
        int x = t & 3, y = t >> 2;
        float4 a = s5[(2 * y) * 8 + 2 * x],     b = s5[(2 * y) * 8 + 2 * x + 1];
        float4 c = s5[(2 * y + 1) * 8 + 2 * x], d = s5[(2 * y + 1) * 8 + 2 * x + 1];
        float4 v = make_float4((a.x + b.x + c.x + d.x) * 0.25f,
                               (a.y + b.y + c.y + d.y) * 0.25f,
                               (a.z + b.z + c.z + d.z) * 0.25f, 0.0f);
        L6[(size_t)(4 * by + y) * 64 + (4 * bx + x)] = pack_h4(v.x, v.y, v.z);
        s6[y * 4 + x] = v;
    }
    __syncthreads();

    if (t < 4) {
        int x = t & 1, y = t >> 1;
        float4 a = s6[(2 * y) * 4 + 2 * x],     b = s6[(2 * y) * 4 + 2 * x + 1];
        float4 c = s6[(2 * y + 1) * 4 + 2 * x], d = s6[(2 * y + 1) * 4 + 2 * x + 1];
        float4 v = make_float4((a.x + b.x + c.x + d.x) * 0.25f,
                               (a.y + b.y + c.y + d.y) * 0.25f,
                               (a.z + b.z + c.z + d.z) * 0.25f, 0.0f);
        L7[(size_t)(2 * by + y) * 32 + (2 * bx + x)] = pack_h4(v.x, v.y, v.z);
        s7[y * 2 + x] = v;
    }
    __syncthreads();

    if (t == 0) {
        float4 a = s7[0], b = s7[1], c = s7[2], d = s7[3];
        L8[(size_t)by * 16 + bx] = pack_h4((a.x + b.x + c.x + d.x) * 0.25f,
                                           (a.y + b.y + c.y + d.y) * 0.25f,
                                           (a.z + b.z + c.z + d.z) * 0.25f);
    }
}

// Bilinear fetch (wrap) from fp16 mip storage. One 8B load per tap.
__device__ __forceinline__ void vt_bilinear_h(const h4* __restrict__ tex, int w,
                                              float u, float v, float rgb[3]) {
    float x = u * (float)w - 0.5f;
    float y = v * (float)w - 0.5f;
    float x0f = floorf(x);
    float y0f = floorf(y);
    float fx = x - x0f;
    float fy = y - y0f;
    int x0 = (int)x0f;
    int y0 = (int)y0f;
    if (x0 < 0) x0 += w;
    if (y0 < 0) y0 += w;
    int x1 = x0 + 1; if (x1 == w) x1 = 0;
    int y1 = y0 + 1; if (y1 == w) y1 = 0;

    float3 p00 = unpack_h4(tex[(size_t)y0 * w + x0]);
    float3 p01 = unpack_h4(tex[(size_t)y0 * w + x1]);
    float3 p10 = unpack_h4(tex[(size_t)y1 * w + x0]);
    float3 p11 = unpack_h4(tex[(size_t)y1 * w + x1]);

    float w00 = (1.0f - fx) * (1.0f - fy);
    float w01 = fx * (1.0f - fy);
    float w10 = (1.0f - fx) * fy;
    float w11 = fx * fy;

    rgb[0] = p00.x * w00 + p01.x * w01 + p10.x * w10 + p11.x * w11;
    rgb[1] = p00.y * w00 + p01.y * w01 + p10.y * w10 + p11.y * w11;
    rgb[2] = p00.z * w00 + p01.z * w01 + p10.z * w10 + p11.z * w11;
}

// Packed fp32 bilinear for level 0 only (rare path, exact).
__device__ __forceinline__ void vt_bilinear0(const float* __restrict__ tex, int w,
                                             float u, float v, float rgb[3]) {
    float x = u * (float)w - 0.5f;
    float y = v * (float)w - 0.5f;
    float x0f = floorf(x);
    float y0f = floorf(y);
    float fx = x - x0f;
    float fy = y - y0f;
    int x0 = (int)x0f;
    int y0 = (int)y0f;
    if (x0 < 0) x0 += w;
    if (y0 < 0) y0 += w;
    int x1 = x0 + 1; if (x1 == w) x1 = 0;
    int y1 = y0 + 1; if (y1 == w) y1 = 0;

    const float* p00 = tex + ((size_t)y0 * w + x0) * 3;
    const float* p01 = tex + ((size_t)y0 * w + x1) * 3;
    const float* p10 = tex + ((size_t)y1 * w + x0) * 3;
    const float* p11 = tex + ((size_t)y1 * w + x1) * 3;

    float w00 = (1.0f - fx) * (1.0f - fy);
    float w01 = fx * (1.0f - fy);
    float w10 = (1.0f - fx) * fy;
    float w11 = fx * fy;

#pragma unroll
    for (int c = 0; c < 3; c++)
        rgb[c] = p00[c] * w00 + p01[c] * w01 + p10[c] * w10 + p11[c] * w11;
}

__global__ __launch_bounds__(256) void vt_sample(const float* __restrict__ data,
                          const float2* __restrict__ texc,
                          const float4* __restrict__ deriv,
                          float* __restrict__ out) {
    int i = blockIdx.x * blockDim.x + threadIdx.x;
    if (i >= OUTW * OUTW) return;

    float2 uv = texc[i];
    float4 d = deriv[i];

    float dudx = d.x * (float)W0;
    float dvdx = d.y * (float)W0;
    float dudy = d.z * (float)W0;
    float dvdy = d.w * (float)W0;

    float rho2 = fmaxf(dudx * dudx + dvdx * dvdx, dudy * dudy + dvdy * dvdy);
    float lod = 0.5f * __log2f(fmaxf(rho2, 1e-20f));
    lod = fminf(fmaxf(lod, 0.0f), (float)MAXMIP);

    int l0 = (int)lod;
    if (l0 > MAXMIP) l0 = MAXMIP;
    float frac = lod - (float)l0;
    int l1 = (l0 < MAXMIP) ? (l0 + 1) : MAXMIP;

    float a[3], b[3];
    if (l0 == 0) {
        vt_bilinear0(data, W0, uv.x, uv.y, a);
    } else {
        vt_bilinear_h(g_mh + MIPH_OFF[l0], W0 >> l0, uv.x, uv.y, a);
    }
    vt_bilinear_h(g_mh + MIPH_OFF[l1], W0 >> l1, uv.x, uv.y, b);

    float w0 = 1.0f - frac;
    out[(size_t)3 * i + 0] = a[0] * w0 + b[0] * frac;
    out[(size_t)3 * i + 1] = a[1] * w0 + b[1] * frac;
    out[(size_t)3 * i + 2] = a[2] * w0 + b[2] * frac;
}

extern "C" void kernel_launch(void* const* d_in, const int* in_sizes, int n_in,
                              void* d_out, int out_size) {
    const float* data  = (const float*)d_in[0];   // [1,4096,4096,3]
    const float2* texc = (const float2*)d_in[1];  // [1,1024,1024,2]
    const float4* deriv = (const float4*)d_in[2]; // [1,1024,1024,4]
    float* out = (float*)d_out;                   // [1,1024,1024,3]

    (void)in_sizes; (void)n_in; (void)out_size;

    // A: base -> L1, L2
    vt_downA<<<4096, 256>>>(data);
    // B: L2 -> L3..L8
    {
        dim3 grid(16, 16);
        vt_downB<<<grid, 256>>>();
    }
    // Trilinear sample
    vt_sample<<<4096, 256>>>(data, texc, deriv, out);
}